// round 16
// baseline (speedup 1.0000x reference)
#include <cuda_runtime.h>
#include <cstdint>

#define BATCH 256
#define TSTEPS 1024
#define HID 64
#define DIN 3

// Scratch (device globals — no cudaMalloc allowed).
__device__ float g_h2[BATCH * TSTEPS * HID];

typedef unsigned long long u64;

// ---- packed fp32x2 helpers (ptxas never auto-emits FFMA2) ----
__device__ __forceinline__ u64 fma2(u64 a, u64 b, u64 c) {
    u64 d; asm("fma.rn.f32x2 %0, %1, %2, %3;" : "=l"(d) : "l"(a), "l"(b), "l"(c)); return d;
}
__device__ __forceinline__ u64 add2(u64 a, u64 b) {
    u64 d; asm("add.rn.f32x2 %0, %1, %2;" : "=l"(d) : "l"(a), "l"(b)); return d;
}
__device__ __forceinline__ u64 packf2(float lo, float hi) {
    u64 d; asm("mov.b64 %0, {%1, %2};" : "=l"(d) : "f"(lo), "f"(hi)); return d;
}
__device__ __forceinline__ float2 unpackf2(u64 v) {
    float2 f; asm("mov.b64 {%0, %1}, %2;" : "=f"(f.x), "=f"(f.y) : "l"(v)); return f;
}
__device__ __forceinline__ void lds2(u64 &a, u64 &b, uint32_t addr) {
    asm volatile("ld.shared.v2.b64 {%0, %1}, [%2];" : "=l"(a), "=l"(b) : "r"(addr));
}

// ---- single-MUFU activations (tanh.approx) ----
__device__ __forceinline__ float tanha(float x) {
    float r; asm("tanh.approx.f32 %0, %1;" : "=f"(r) : "f"(x)); return r;
}
__device__ __forceinline__ float siga(float x) {
    return fmaf(0.5f, tanha(0.5f * x), 0.5f);
}

// ============================================================================
// Fused 2-layer LSTM, k-split: 512 threads/CTA, thread = (row, k-half).
// Each thread owns the 32-float k-half of its row of Whh0/Wih1/Whh1
// (48 u64 = 96 weight regs; total weight storage conserved vs champion).
// 16 warps = 4 warps/SMSP (vs 2) -> serial epilogue chains hidden better.
// Partial dots combined via shfl_xor(1): partner = same row, other k-half,
// adjacent lane (lane = 2*(row%16) + khalf by construction).
// Lane khalf handles seq==khalf activations (2 act + 2 STS per thread).
// Pipeline & cell phase identical to the 793us champion (cells = tid<256).
// ============================================================================
__global__ void __launch_bounds__(512, 1) lstm_fused(
    const float* __restrict__ x,
    const float* __restrict__ Wih0, const float* __restrict__ Whh0,
    const float* __restrict__ bih0, const float* __restrict__ bhh0,
    const float* __restrict__ Wih1, const float* __restrict__ Whh1,
    const float* __restrict__ bih1, const float* __restrict__ bhh1)
{
    __shared__ __align__(16) float sx[2][TSTEPS * DIN];  // 24 KB
    __shared__ __align__(16) float sh1[2][HID];
    __shared__ __align__(16) float sh2[2][HID];
    __shared__ __align__(16) float sg1[2][256];
    __shared__ __align__(16) float sg2[2][256];
    const int tid = threadIdx.x;
    const int row = tid >> 1;
    const int kh = tid & 1;
    const int b0 = blockIdx.x * 2;

    // stage both sequences' inputs (1536 float4 tasks, 512 threads x 3)
    {
        const float4* xs0 = (const float4*)(x + (size_t)b0 * TSTEPS * DIN);
        const float4* xs1 = (const float4*)(x + (size_t)(b0 + 1) * TSTEPS * DIN);
        #pragma unroll
        for (int i = 0; i < 3; i++) {
            int task = tid + i * 512;
            int seq = task >= 768;
            int off = task - seq * 768;
            ((float4*)sx[seq])[off] = seq ? xs1[off] : xs0[off];
        }
    }

    // per-thread weight half-rows, packed f32x2 along k
    u64 w0[16], wA[16], wB[16];
    {
        const float4* r0 = (const float4*)(Whh0 + row * HID + kh * 32);
        const float4* rA = (const float4*)(Wih1 + row * HID + kh * 32);
        const float4* rB = (const float4*)(Whh1 + row * HID + kh * 32);
        #pragma unroll
        for (int i = 0; i < 8; i++) {
            float4 v = r0[i]; w0[2*i] = packf2(v.x, v.y); w0[2*i+1] = packf2(v.z, v.w);
            float4 a = rA[i]; wA[2*i] = packf2(a.x, a.y); wA[2*i+1] = packf2(a.z, a.w);
            float4 b = rB[i]; wB[2*i] = packf2(b.x, b.y); wB[2*i+1] = packf2(b.z, b.w);
        }
    }
    const float wx0 = Wih0[row * 3 + 0], wx1 = Wih0[row * 3 + 1], wx2 = Wih0[row * 3 + 2];
    const float bias0 = bih0[row] + bhh0[row];
    const float bias1 = bih1[row] + bhh1[row];
    const int gtype = row >> 6;   // warp-uniform (16 consecutive rows per warp)

    // cell role (threads 0..255 only): tid -> (layer, seq, m)
    const int cl_layer = tid >> 7;
    const int cl_b = (tid >> 6) & 1;
    const int cl_m = tid & 63;
    float c = 0.0f;

    if (tid < 128)       ((float*)sh1)[tid] = 0.0f;
    else if (tid < 256)  ((float*)sh2)[tid - 128] = 0.0f;

    // smem addresses with my k-half offset baked in (half = 32 floats = 128 B)
    const uint32_t a_h1s0 = (uint32_t)__cvta_generic_to_shared(&sh1[0][0]) + (uint32_t)kh * 128u;
    const uint32_t a_h1s1 = (uint32_t)__cvta_generic_to_shared(&sh1[1][0]) + (uint32_t)kh * 128u;
    const uint32_t a_h2s0 = (uint32_t)__cvta_generic_to_shared(&sh2[0][0]) + (uint32_t)kh * 128u;
    const uint32_t a_h2s1 = (uint32_t)__cvta_generic_to_shared(&sh2[1][0]) + (uint32_t)kh * 128u;
    __syncthreads();

    #pragma unroll 1
    for (int t = 0; t <= TSTEPS; t++) {
        // ---- gate phase: 6 partial dots over my 32-float k-half (96 fma2) --
        u64 A0 = 0, A1 = 0, B0 = 0, B1 = 0, C0 = 0, C1 = 0;
        #pragma unroll
        for (int kk = 0; kk < 8; kk++) {
            {   // seq 0 half-phase (keeps live temps at 4 u64)
                u64 p0, p1, r0, r1;
                lds2(p0, p1, a_h1s0 + kk * 16);
                lds2(r0, r1, a_h2s0 + kk * 16);
                A0 = fma2(w0[2*kk],     p0, A0);
                A0 = fma2(w0[2*kk + 1], p1, A0);
                B0 = fma2(wA[2*kk],     p0, B0);
                B0 = fma2(wA[2*kk + 1], p1, B0);
                C0 = fma2(wB[2*kk],     r0, C0);
                C0 = fma2(wB[2*kk + 1], r1, C0);
            }
            {   // seq 1 half-phase
                u64 q0, q1, s0, s1;
                lds2(q0, q1, a_h1s1 + kk * 16);
                lds2(s0, s1, a_h2s1 + kk * 16);
                A1 = fma2(w0[2*kk],     q0, A1);
                A1 = fma2(w0[2*kk + 1], q1, A1);
                B1 = fma2(wA[2*kk],     q0, B1);
                B1 = fma2(wA[2*kk + 1], q1, B1);
                C1 = fma2(wB[2*kk],     s0, C1);
                C1 = fma2(wB[2*kk + 1], s1, C1);
            }
        }
        // drain: horizontal sums of my partials, then cross-half combine
        float2 fA0 = unpackf2(A0), fA1 = unpackf2(A1);
        float2 f20 = unpackf2(add2(B0, C0));
        float2 f21 = unpackf2(add2(B1, C1));
        float sA0 = fA0.x + fA0.y;
        float sA1 = fA1.x + fA1.y;
        float s20 = f20.x + f20.y;
        float s21 = f21.x + f21.y;
        sA0 += __shfl_xor_sync(0xffffffffu, sA0, 1);
        sA1 += __shfl_xor_sync(0xffffffffu, sA1, 1);
        s20 += __shfl_xor_sync(0xffffffffu, s20, 1);
        s21 += __shfl_xor_sync(0xffffffffu, s21, 1);

        // lane kh handles seq==kh: 2 activations + 2 STS per thread
        const int tx = (t < TSTEPS) ? t : (TSTEPS - 1);
        const float* sxm = sx[kh];
        float pre1 = (kh ? sA1 : sA0) + bias0
                   + wx0 * sxm[tx*3] + wx1 * sxm[tx*3 + 1] + wx2 * sxm[tx*3 + 2];
        float pre2 = (kh ? s21 : s20) + bias1;
        float v1, v2;
        if (gtype == 2) { v1 = tanha(pre1); v2 = tanha(pre2); }
        else            { v1 = siga(pre1);  v2 = siga(pre2);  }
        sg1[kh][row] = v1;
        sg2[kh][row] = v2;
        __syncthreads();

        // ---- cell phase: threads 0..255, one cell each (warp-uniform roles)
        if (tid < 256) {
            bool active = cl_layer ? (t >= 1) : (t < TSTEPS);
            if (active) {
                const float* Gp = cl_layer ? sg2[cl_b] : sg1[cl_b];
                float iv = Gp[cl_m], fv = Gp[cl_m + 64];
                float gv = Gp[cl_m + 128], ov = Gp[cl_m + 192];
                c = fmaf(fv, c, iv * gv);
                float hn = ov * tanha(c);
                if (cl_layer) {
                    sh2[cl_b][cl_m] = hn;
                    g_h2[((size_t)(b0 + cl_b) * TSTEPS + (size_t)(t - 1)) * HID + cl_m] = hn;
                } else {
                    sh1[cl_b][cl_m] = hn;
                }
            }
        }
        __syncthreads();
    }
}

// ============================================================================
// Output projection, fp32 + MLP=8 (validated R15: 18us).
// ============================================================================
#define PROJ_GROUPS (BATCH * TSTEPS / 8)   // 32768 row-groups of 8 rows
__global__ void __launch_bounds__(256) proj_kernel(
    const float* __restrict__ Wout, const float* __restrict__ bout,
    float* __restrict__ y)
{
    __shared__ float sw[3 * 64];
    __shared__ float sb[3];
    const int tid = threadIdx.x;
    if (tid < 192) sw[tid] = Wout[tid];
    if (tid < 3)   sb[tid] = bout[tid];
    __syncthreads();

    const int gg = blockIdx.x * 256 + tid;
    const int grp = gg >> 4;
    const int l = gg & 15;

    float4 hv[8];
    #pragma unroll
    for (int k = 0; k < 8; k++) {
        size_t r = (size_t)grp + (size_t)k * PROJ_GROUPS;
        hv[k] = *(const float4*)&g_h2[r * HID + l * 4];
    }

    const int s4 = l * 4;
    const float* w0r = &sw[s4];
    const float* w1r = &sw[64 + s4];
    const float* w2r = &sw[128 + s4];

    #pragma unroll
    for (int k = 0; k < 8; k++) {
        float4 v = hv[k];
        float a0 = w0r[0]*v.x + w0r[1]*v.y + w0r[2]*v.z + w0r[3]*v.w;
        float a1 = w1r[0]*v.x + w1r[1]*v.y + w1r[2]*v.z + w1r[3]*v.w;
        float a2 = w2r[0]*v.x + w2r[1]*v.y + w2r[2]*v.z + w2r[3]*v.w;
        #pragma unroll
        for (int o = 8; o > 0; o >>= 1) {
            a0 += __shfl_xor_sync(0xffffffffu, a0, o);
            a1 += __shfl_xor_sync(0xffffffffu, a1, o);
            a2 += __shfl_xor_sync(0xffffffffu, a2, o);
        }
        if (l == 0) {
            size_t r = (size_t)grp + (size_t)k * PROJ_GROUPS;
            y[r * 3 + 0] = a0 + sb[0];
            y[r * 3 + 1] = a1 + sb[1];
            y[r * 3 + 2] = a2 + sb[2];
        }
    }
}

extern "C" void kernel_launch(void* const* d_in, const int* in_sizes, int n_in,
                              void* d_out, int out_size)
{
    const float* x    = (const float*)d_in[0];
    const float* Wih0 = (const float*)d_in[1];
    const float* Whh0 = (const float*)d_in[2];
    const float* bih0 = (const float*)d_in[3];
    const float* bhh0 = (const float*)d_in[4];
    const float* Wih1 = (const float*)d_in[5];
    const float* Whh1 = (const float*)d_in[6];
    const float* bih1 = (const float*)d_in[7];
    const float* bhh1 = (const float*)d_in[8];
    const float* Wout = (const float*)d_in[9];
    const float* bout = (const float*)d_in[10];
    float* y = (float*)d_out;

    lstm_fused<<<BATCH / 2, 512>>>(x, Wih0, Whh0, bih0, bhh0,
                                   Wih1, Whh1, bih1, bhh1);
    proj_kernel<<<(BATCH * TSTEPS * 16) / 8 / 256, 256>>>(Wout, bout, y);
}